// round 15
// baseline (speedup 1.0000x reference)
#include <cuda_runtime.h>
#include <math.h>

// Problem constants (fixed shapes per reference)
#define NN 100000          // nodes
#define NE 1600000         // edges
#define DIN 128
#define DHID 32
#define NEG_SLOPE 0.2f

typedef unsigned long long u64;

// ---------------- device scratch (static allocation, allowed) ----------------
__device__ int   g_deg[NN];
__device__ int   g_cursor[NN];
__device__ int   g_rowptr[NN + 1];
__device__ int   g_bsums[128];
__device__ int   g_csr_src[NE];
__device__ int   g_is64;           // 1 if edge_index is int64, 0 if int32
__device__ float g_xl[NN * DHID];
__device__ float g_xr[NN * DHID];
__device__ float g_h[NN * DHID];

// ---------------- f32x2 packed math (Blackwell FFMA2, PTX-only) --------------
__device__ __forceinline__ u64 fma2(u64 a, u64 b, u64 c) {
    u64 d;
    asm("fma.rn.f32x2 %0, %1, %2, %3;" : "=l"(d) : "l"(a), "l"(b), "l"(c));
    return d;
}
__device__ __forceinline__ float unpack_sum(u64 a) {
    float lo, hi;
    asm("mov.b64 {%0,%1}, %2;" : "=f"(lo), "=f"(hi) : "l"(a));
    return lo + hi;
}

// leaky_relu(h) = max(h, 0.2h)  (exact for all finite h since slope in (0,1))
__device__ __forceinline__ float lrelu(float h) {
    return fmaxf(h, NEG_SLOPE * h);
}

// ---------------- init: zero degree counters + detect edge dtype -------------
// int64 values < 2^31 => every odd 32-bit word is 0. int32 data: essentially
// impossible for 2048 sampled odd words to all be zero.
__global__ void init_k(const unsigned int* __restrict__ w) {
    int i = blockIdx.x * blockDim.x + threadIdx.x;
    if (i < NN) g_deg[i] = 0;
    if (blockIdx.x == 0) {
        __shared__ int allz;
        if (threadIdx.x == 0) allz = 1;
        __syncthreads();
        for (int k = threadIdx.x; k < 2048; k += blockDim.x) {
            if (w[2 * k + 1] != 0u) allz = 0;
        }
        __syncthreads();
        if (threadIdx.x == 0) g_is64 = allz;
    }
}

// ---------------- CSR build ----------------
__global__ void hist_k(const void* __restrict__ ei) {
    int t = blockIdx.x * blockDim.x + threadIdx.x;   // edges 2t, 2t+1
    if (2 * t >= NE) return;
    int d0, d1;
    if (g_is64) {
        longlong2 v = __ldg(&((const longlong2*)((const long long*)ei + NE))[t]);
        d0 = (int)v.x; d1 = (int)v.y;
    } else {
        int2 v = __ldg(&((const int2*)((const int*)ei + NE))[t]);
        d0 = v.x; d1 = v.y;
    }
    atomicAdd(&g_deg[d0], 1);
    atomicAdd(&g_deg[d1], 1);
}

__global__ void scan_local_k() {            // grid: ceil(NN/1024), block: 1024
    __shared__ int wsum[32];
    int tid = threadIdx.x;
    int i = blockIdx.x * 1024 + tid;
    int v = (i < NN) ? g_deg[i] : 0;
    int lane = tid & 31, wid = tid >> 5;
    int x = v;
    #pragma unroll
    for (int off = 1; off < 32; off <<= 1) {       // inclusive warp scan
        int t = __shfl_up_sync(0xffffffffu, x, off);
        if (lane >= off) x += t;
    }
    if (lane == 31) wsum[wid] = x;
    __syncthreads();
    if (wid == 0) {
        int s = wsum[lane];
        #pragma unroll
        for (int off = 1; off < 32; off <<= 1) {
            int t = __shfl_up_sync(0xffffffffu, s, off);
            if (lane >= off) s += t;
        }
        wsum[lane] = s;
    }
    __syncthreads();
    int incl = x + (wid > 0 ? wsum[wid - 1] : 0);
    if (i < NN) g_rowptr[i] = incl - v;            // exclusive
    if (tid == 1023) g_bsums[blockIdx.x] = incl;
}

// Adds the cross-block prefix (computed in-kernel from g_bsums) and seeds the
// scatter cursors. Replaces the separate scan_bsums kernel.
__global__ void add_offsets_k() {           // grid: ceil(NN/1024), block: 1024
    __shared__ int s_base;
    int b = blockIdx.x;
    if (threadIdx.x < 32) {
        int acc = 0;
        for (int j = (int)threadIdx.x; j < b; j += 32) acc += g_bsums[j];
        #pragma unroll
        for (int off = 16; off > 0; off >>= 1)
            acc += __shfl_xor_sync(0xffffffffu, acc, off);
        if (threadIdx.x == 0) s_base = acc;
    }
    __syncthreads();
    int i = b * 1024 + threadIdx.x;
    if (i < NN) {
        int r = g_rowptr[i] + s_base;
        g_rowptr[i] = r;
        g_cursor[i] = r;                           // scatter bumps this directly
    }
    if (i == 0) g_rowptr[NN] = NE;
}

__global__ void scatter_k(const void* __restrict__ ei) {
    int t = blockIdx.x * blockDim.x + threadIdx.x;   // edges 2t, 2t+1
    if (2 * t >= NE) return;
    int s0, s1, d0, d1;
    if (g_is64) {
        longlong2 sv = __ldg(&((const longlong2*)ei)[t]);
        longlong2 dv = __ldg(&((const longlong2*)((const long long*)ei + NE))[t]);
        s0 = (int)sv.x; s1 = (int)sv.y;
        d0 = (int)dv.x; d1 = (int)dv.y;
    } else {
        int2 sv = __ldg(&((const int2*)ei)[t]);
        int2 dv = __ldg(&((const int2*)((const int*)ei + NE))[t]);
        s0 = sv.x; s1 = sv.y;
        d0 = dv.x; d1 = dv.y;
    }
    int p0 = atomicAdd(&g_cursor[d0], 1);
    g_csr_src[p0] = s0;
    int p1 = atomicAdd(&g_cursor[d1], 1);
    g_csr_src[p1] = s1;
}

// ---------------- dual GEMM: OL = X @ Wl, OR = X @ Wr  (X: [NN,K], W: [K,32]) --
// Packed f32x2 FMAs; weights staged pre-packed as (w[k],w[k+1]) pairs, x rows
// read as ulonglong2 (one LDS.128 = two f32x2 operands).
template <int K>
__global__ void gemm_dual_k(const float* __restrict__ X,
                            const float* __restrict__ Wl,
                            const float* __restrict__ Wr,
                            float* __restrict__ OL,
                            float* __restrict__ ORr) {
    constexpr int TN = 64;                  // nodes per block
    extern __shared__ float smem[];
    float* s_x  = smem;                     // TN*K
    float* s_wl = smem + TN * K;            // K*32 floats (packed pairs)
    float* s_wr = s_wl + K * 32;            // K*32

    int tid = threadIdx.x;                  // 256 threads
    for (int idx = tid; idx < (K / 2) * 32; idx += 256) {
        int k2 = idx >> 5, l = idx & 31;
        float2 vl = make_float2(Wl[(2 * k2) * 32 + l], Wl[(2 * k2 + 1) * 32 + l]);
        float2 vr = make_float2(Wr[(2 * k2) * 32 + l], Wr[(2 * k2 + 1) * 32 + l]);
        reinterpret_cast<float2*>(s_wl)[idx] = vl;
        reinterpret_cast<float2*>(s_wr)[idx] = vr;
    }
    int nb = blockIdx.x * TN;
    const float4* X4 = reinterpret_cast<const float4*>(X);
    float4* sx4 = reinterpret_cast<float4*>(s_x);
    int base4 = nb * (K / 4);
    int lim4 = NN * (K / 4) - base4;        // valid float4s left in X
    for (int idx = tid; idx < TN * (K / 4); idx += 256) {
        sx4[idx] = (idx < lim4) ? X4[base4 + idx] : make_float4(0.f, 0.f, 0.f, 0.f);
    }
    __syncthreads();

    int w = tid >> 5, lane = tid & 31;
    u64 aL[8], aR[8];
    #pragma unroll
    for (int j = 0; j < 8; j++) { aL[j] = 0ull; aR[j] = 0ull; }
    const float* xrow = &s_x[(w * 8) * K];
    const u64* wl2 = reinterpret_cast<const u64*>(s_wl);
    const u64* wr2 = reinterpret_cast<const u64*>(s_wr);

    #pragma unroll 4
    for (int i = 0; i < K; i += 4) {
        u64 wl01 = wl2[(i >> 1) * 32 + lane];
        u64 wl23 = wl2[((i >> 1) + 1) * 32 + lane];
        u64 wr01 = wr2[(i >> 1) * 32 + lane];
        u64 wr23 = wr2[((i >> 1) + 1) * 32 + lane];
        #pragma unroll
        for (int j = 0; j < 8; j++) {
            ulonglong2 xv = *reinterpret_cast<const ulonglong2*>(&xrow[j * K + i]);
            aL[j] = fma2(xv.x, wl01, aL[j]);
            aL[j] = fma2(xv.y, wl23, aL[j]);
            aR[j] = fma2(xv.x, wr01, aR[j]);
            aR[j] = fma2(xv.y, wr23, aR[j]);
        }
    }
    #pragma unroll
    for (int j = 0; j < 8; j++) {
        int node = nb + w * 8 + j;
        if (node < NN) {
            OL[node * 32 + lane]  = unpack_sum(aL[j]);
            ORr[node * 32 + lane] = unpack_sum(aR[j]);
        }
    }
}

// ---------------- GATv2 edge pass ----------------
// Warp = dst node, split into 4 groups of 8 lanes. Each group owns a strided
// quarter of the node's incoming edges; float4-per-lane features. Group-local
// dot = 3-step shfl butterfly with the GROUP mask (groups diverge). Softmax
// without max subtraction (logits bounded; acc/s cancels scale exactly).
// Main loop unrolled x4 for gather MLP against ~250cyc L2 latency.
template <bool RELU>
__global__ void gat_edge_k(const float* __restrict__ xl,
                           const float* __restrict__ xr,
                           const float* __restrict__ att,
                           const float* __restrict__ bias,
                           float* __restrict__ out) {
    const unsigned FULL = 0xffffffffu;
    int gw = (blockIdx.x * blockDim.x + threadIdx.x) >> 5;
    int lane = threadIdx.x & 31;
    if (gw >= NN) return;
    int n = gw;
    int grp = lane >> 3;                    // 0..3
    int sub = lane & 7;                     // 0..7 -> features sub*4..sub*4+3
    const unsigned gmask = 0xffu << (grp * 8);   // this group's 8 lanes

    float4 xr4 = *reinterpret_cast<const float4*>(&xr[n * 32 + sub * 4]);
    float4 at4 = *reinterpret_cast<const float4*>(&att[sub * 4]);

    int e0 = g_rowptr[n], e1 = g_rowptr[n + 1];

    float ssum = 0.f;
    float4 acc = make_float4(0.f, 0.f, 0.f, 0.f);

    int e = e0 + grp;                       // this group's strided edges, step 4

    // ---- 4-edge unrolled main loop (4 gathers in flight per group) ----
    for (; e + 12 < e1; e += 16) {
        int s0 = __ldg(&g_csr_src[e]);
        int s1 = __ldg(&g_csr_src[e + 4]);
        int s2 = __ldg(&g_csr_src[e + 8]);
        int s3 = __ldg(&g_csr_src[e + 12]);
        float4 x0 = *reinterpret_cast<const float4*>(&xl[s0 * 32 + sub * 4]);
        float4 x1 = *reinterpret_cast<const float4*>(&xl[s1 * 32 + sub * 4]);
        float4 x2 = *reinterpret_cast<const float4*>(&xl[s2 * 32 + sub * 4]);
        float4 x3 = *reinterpret_cast<const float4*>(&xl[s3 * 32 + sub * 4]);
        float d0, d1, d2, d3;
        d0  = lrelu(x0.x + xr4.x) * at4.x;
        d0 += lrelu(x0.y + xr4.y) * at4.y;
        d0 += lrelu(x0.z + xr4.z) * at4.z;
        d0 += lrelu(x0.w + xr4.w) * at4.w;
        d1  = lrelu(x1.x + xr4.x) * at4.x;
        d1 += lrelu(x1.y + xr4.y) * at4.y;
        d1 += lrelu(x1.z + xr4.z) * at4.z;
        d1 += lrelu(x1.w + xr4.w) * at4.w;
        d2  = lrelu(x2.x + xr4.x) * at4.x;
        d2 += lrelu(x2.y + xr4.y) * at4.y;
        d2 += lrelu(x2.z + xr4.z) * at4.z;
        d2 += lrelu(x2.w + xr4.w) * at4.w;
        d3  = lrelu(x3.x + xr4.x) * at4.x;
        d3 += lrelu(x3.y + xr4.y) * at4.y;
        d3 += lrelu(x3.z + xr4.z) * at4.z;
        d3 += lrelu(x3.w + xr4.w) * at4.w;
        d0 += __shfl_xor_sync(gmask, d0, 1);
        d1 += __shfl_xor_sync(gmask, d1, 1);
        d2 += __shfl_xor_sync(gmask, d2, 1);
        d3 += __shfl_xor_sync(gmask, d3, 1);
        d0 += __shfl_xor_sync(gmask, d0, 2);
        d1 += __shfl_xor_sync(gmask, d1, 2);
        d2 += __shfl_xor_sync(gmask, d2, 2);
        d3 += __shfl_xor_sync(gmask, d3, 2);
        d0 += __shfl_xor_sync(gmask, d0, 4);
        d1 += __shfl_xor_sync(gmask, d1, 4);
        d2 += __shfl_xor_sync(gmask, d2, 4);
        d3 += __shfl_xor_sync(gmask, d3, 4);
        float ex0 = __expf(d0), ex1 = __expf(d1);
        float ex2 = __expf(d2), ex3 = __expf(d3);
        ssum += (ex0 + ex1) + (ex2 + ex3);
        acc.x = fmaf(ex0, x0.x, fmaf(ex1, x1.x, fmaf(ex2, x2.x, fmaf(ex3, x3.x, acc.x))));
        acc.y = fmaf(ex0, x0.y, fmaf(ex1, x1.y, fmaf(ex2, x2.y, fmaf(ex3, x3.y, acc.y))));
        acc.z = fmaf(ex0, x0.z, fmaf(ex1, x1.z, fmaf(ex2, x2.z, fmaf(ex3, x3.z, acc.z))));
        acc.w = fmaf(ex0, x0.w, fmaf(ex1, x1.w, fmaf(ex2, x2.w, fmaf(ex3, x3.w, acc.w))));
    }
    // ---- 2-edge loop ----
    for (; e + 4 < e1; e += 8) {
        int s0 = __ldg(&g_csr_src[e]);
        int s1 = __ldg(&g_csr_src[e + 4]);
        float4 x0 = *reinterpret_cast<const float4*>(&xl[s0 * 32 + sub * 4]);
        float4 x1 = *reinterpret_cast<const float4*>(&xl[s1 * 32 + sub * 4]);
        float d0, d1;
        d0  = lrelu(x0.x + xr4.x) * at4.x;
        d0 += lrelu(x0.y + xr4.y) * at4.y;
        d0 += lrelu(x0.z + xr4.z) * at4.z;
        d0 += lrelu(x0.w + xr4.w) * at4.w;
        d1  = lrelu(x1.x + xr4.x) * at4.x;
        d1 += lrelu(x1.y + xr4.y) * at4.y;
        d1 += lrelu(x1.z + xr4.z) * at4.z;
        d1 += lrelu(x1.w + xr4.w) * at4.w;
        d0 += __shfl_xor_sync(gmask, d0, 1);
        d1 += __shfl_xor_sync(gmask, d1, 1);
        d0 += __shfl_xor_sync(gmask, d0, 2);
        d1 += __shfl_xor_sync(gmask, d1, 2);
        d0 += __shfl_xor_sync(gmask, d0, 4);
        d1 += __shfl_xor_sync(gmask, d1, 4);
        float ex0 = __expf(d0), ex1 = __expf(d1);
        ssum += ex0 + ex1;
        acc.x = fmaf(ex0, x0.x, fmaf(ex1, x1.x, acc.x));
        acc.y = fmaf(ex0, x0.y, fmaf(ex1, x1.y, acc.y));
        acc.z = fmaf(ex0, x0.z, fmaf(ex1, x1.z, acc.z));
        acc.w = fmaf(ex0, x0.w, fmaf(ex1, x1.w, acc.w));
    }
    if (e < e1) {                           // group tail: single edge
        int s0 = __ldg(&g_csr_src[e]);
        float4 x0 = *reinterpret_cast<const float4*>(&xl[s0 * 32 + sub * 4]);
        float d0;
        d0  = lrelu(x0.x + xr4.x) * at4.x;
        d0 += lrelu(x0.y + xr4.y) * at4.y;
        d0 += lrelu(x0.z + xr4.z) * at4.z;
        d0 += lrelu(x0.w + xr4.w) * at4.w;
        d0 += __shfl_xor_sync(gmask, d0, 1);
        d0 += __shfl_xor_sync(gmask, d0, 2);
        d0 += __shfl_xor_sync(gmask, d0, 4);
        float ex0 = __expf(d0);
        ssum += ex0;
        acc.x = fmaf(ex0, x0.x, acc.x);
        acc.y = fmaf(ex0, x0.y, acc.y);
        acc.z = fmaf(ex0, x0.z, acc.z);
        acc.w = fmaf(ex0, x0.w, acc.w);
    }

    // reconverge the whole warp, then merge the 4 group states (plain sums)
    __syncwarp(FULL);
    float s = ssum;
    s += __shfl_xor_sync(FULL, s, 8);
    s += __shfl_xor_sync(FULL, s, 16);
    acc.x += __shfl_xor_sync(FULL, acc.x, 8);
    acc.y += __shfl_xor_sync(FULL, acc.y, 8);
    acc.z += __shfl_xor_sync(FULL, acc.z, 8);
    acc.w += __shfl_xor_sync(FULL, acc.w, 8);
    acc.x += __shfl_xor_sync(FULL, acc.x, 16);
    acc.y += __shfl_xor_sync(FULL, acc.y, 16);
    acc.z += __shfl_xor_sync(FULL, acc.z, 16);
    acc.w += __shfl_xor_sync(FULL, acc.w, 16);

    if (grp == 0) {                         // lanes 0..7 store the 32 features
        float4 b4 = *reinterpret_cast<const float4*>(&bias[sub * 4]);
        float inv = 1.f / (s + 1e-16f);
        float4 o;
        o.x = acc.x * inv + b4.x;
        o.y = acc.y * inv + b4.y;
        o.z = acc.z * inv + b4.z;
        o.w = acc.w * inv + b4.w;
        if (RELU) {
            o.x = fmaxf(o.x, 0.f); o.y = fmaxf(o.y, 0.f);
            o.z = fmaxf(o.z, 0.f); o.w = fmaxf(o.w, 0.f);
        }
        *reinterpret_cast<float4*>(&out[n * 32 + sub * 4]) = o;
    }
}

// ---------------- launch ----------------
extern "C" void kernel_launch(void* const* d_in, const int* in_sizes, int n_in,
                              void* d_out, int out_size) {
    const float* x    = (const float*)d_in[0];
    const void*  ei   = d_in[1];
    const float* W1l  = (const float*)d_in[2];
    const float* W1r  = (const float*)d_in[3];
    const float* att1 = (const float*)d_in[4];
    const float* b1   = (const float*)d_in[5];
    const float* W2l  = (const float*)d_in[6];
    const float* W2r  = (const float*)d_in[7];
    const float* att2 = (const float*)d_in[8];
    const float* b2   = (const float*)d_in[9];
    float* out = (float*)d_out;

    float *p_xl, *p_xr, *p_h;
    cudaGetSymbolAddress((void**)&p_xl, g_xl);
    cudaGetSymbolAddress((void**)&p_xr, g_xr);
    cudaGetSymbolAddress((void**)&p_h,  g_h);

    cudaFuncSetAttribute(gemm_dual_k<128>,
                         cudaFuncAttributeMaxDynamicSharedMemorySize, 65536);
    cudaFuncSetAttribute(gemm_dual_k<32>,
                         cudaFuncAttributeMaxDynamicSharedMemorySize, 16384);

    // One-time handle creation (no device memory; work per call is identical).
    // First call is the uncaptured correctness run, so creation is outside
    // graph capture.
    static cudaStream_t sCsr = nullptr;
    static cudaEvent_t evFork = nullptr, evCsr = nullptr;
    if (sCsr == nullptr) {
        cudaStreamCreateWithFlags(&sCsr, cudaStreamNonBlocking);
        cudaEventCreateWithFlags(&evFork, cudaEventDisableTiming);
        cudaEventCreateWithFlags(&evCsr, cudaEventDisableTiming);
    }

    const int nscan = (NN + 1023) / 1024;   // 98

    // Fork: CSR build on side stream, GEMM1 on main stream (independent).
    cudaEventRecord(evFork, 0);
    cudaStreamWaitEvent(sCsr, evFork, 0);

    init_k<<<(NN + 255) / 256, 256, 0, sCsr>>>((const unsigned int*)ei);
    hist_k<<<(NE / 2 + 255) / 256, 256, 0, sCsr>>>(ei);
    scan_local_k<<<nscan, 1024, 0, sCsr>>>();
    add_offsets_k<<<nscan, 1024, 0, sCsr>>>();
    scatter_k<<<(NE / 2 + 255) / 256, 256, 0, sCsr>>>(ei);
    cudaEventRecord(evCsr, sCsr);

    gemm_dual_k<128><<<(NN + 63) / 64, 256, 65536>>>(x, W1l, W1r, p_xl, p_xr);

    // Join: edge pass needs both CSR and GEMM1.
    cudaStreamWaitEvent(0, evCsr, 0);
    gat_edge_k<true><<<(NN * 32 + 255) / 256, 256>>>(p_xl, p_xr, att1, b1, p_h);

    // Layer 2
    gemm_dual_k<32><<<(NN + 63) / 64, 256, 16384>>>(p_h, W2l, W2r, p_xl, p_xr);
    gat_edge_k<false><<<(NN * 32 + 255) / 256, 256>>>(p_xl, p_xr, att2, b2, out);
}

// round 16
// speedup vs baseline: 1.0005x; 1.0005x over previous
#include <cuda_runtime.h>
#include <math.h>

// Problem constants (fixed shapes per reference)
#define NN 100000          // nodes
#define NE 1600000         // edges
#define DIN 128
#define DHID 32
#define NEG_SLOPE 0.2f

typedef unsigned long long u64;

// ---------------- device scratch (static allocation, allowed) ----------------
__device__ int   g_deg[NN];
__device__ int   g_cursor[NN];
__device__ int   g_rowptr[NN + 1];
__device__ int   g_bsums[128];
__device__ int   g_csr_src[NE];
__device__ int   g_is64;           // 1 if edge_index is int64, 0 if int32
__device__ float g_xl[NN * DHID];
__device__ float g_xr[NN * DHID];
__device__ float g_h[NN * DHID];

// ---------------- f32x2 packed math (Blackwell FFMA2, PTX-only) --------------
__device__ __forceinline__ u64 fma2(u64 a, u64 b, u64 c) {
    u64 d;
    asm("fma.rn.f32x2 %0, %1, %2, %3;" : "=l"(d) : "l"(a), "l"(b), "l"(c));
    return d;
}
__device__ __forceinline__ float unpack_sum(u64 a) {
    float lo, hi;
    asm("mov.b64 {%0,%1}, %2;" : "=f"(lo), "=f"(hi) : "l"(a));
    return lo + hi;
}

// leaky_relu(h) = max(h, 0.2h)  (exact for all finite h since slope in (0,1))
__device__ __forceinline__ float lrelu(float h) {
    return fmaxf(h, NEG_SLOPE * h);
}

// ---------------- edge dtype detection (deg zeroing is a memset node) --------
// int64 values < 2^31 => every odd 32-bit word is 0. int32 data: essentially
// impossible for 2048 sampled odd words to all be zero.
__global__ void detect_k(const unsigned int* __restrict__ w) {
    __shared__ int allz;
    if (threadIdx.x == 0) allz = 1;
    __syncthreads();
    for (int k = threadIdx.x; k < 2048; k += blockDim.x) {
        if (w[2 * k + 1] != 0u) allz = 0;
    }
    __syncthreads();
    if (threadIdx.x == 0) g_is64 = allz;
}

// ---------------- CSR build ----------------
__global__ void hist_k(const void* __restrict__ ei) {
    int t = blockIdx.x * blockDim.x + threadIdx.x;   // edges 2t, 2t+1
    if (2 * t >= NE) return;
    int d0, d1;
    if (g_is64) {
        longlong2 v = __ldg(&((const longlong2*)((const long long*)ei + NE))[t]);
        d0 = (int)v.x; d1 = (int)v.y;
    } else {
        int2 v = __ldg(&((const int2*)((const int*)ei + NE))[t]);
        d0 = v.x; d1 = v.y;
    }
    atomicAdd(&g_deg[d0], 1);
    atomicAdd(&g_deg[d1], 1);
}

__global__ void scan_local_k() {            // grid: ceil(NN/1024), block: 1024
    __shared__ int wsum[32];
    int tid = threadIdx.x;
    int i = blockIdx.x * 1024 + tid;
    int v = (i < NN) ? g_deg[i] : 0;
    int lane = tid & 31, wid = tid >> 5;
    int x = v;
    #pragma unroll
    for (int off = 1; off < 32; off <<= 1) {       // inclusive warp scan
        int t = __shfl_up_sync(0xffffffffu, x, off);
        if (lane >= off) x += t;
    }
    if (lane == 31) wsum[wid] = x;
    __syncthreads();
    if (wid == 0) {
        int s = wsum[lane];
        #pragma unroll
        for (int off = 1; off < 32; off <<= 1) {
            int t = __shfl_up_sync(0xffffffffu, s, off);
            if (lane >= off) s += t;
        }
        wsum[lane] = s;
    }
    __syncthreads();
    int incl = x + (wid > 0 ? wsum[wid - 1] : 0);
    if (i < NN) g_rowptr[i] = incl - v;            // exclusive
    if (tid == 1023) g_bsums[blockIdx.x] = incl;
}

// Adds the cross-block prefix (computed in-kernel from g_bsums) and seeds the
// scatter cursors.
__global__ void add_offsets_k() {           // grid: ceil(NN/1024), block: 1024
    __shared__ int s_base;
    int b = blockIdx.x;
    if (threadIdx.x < 32) {
        int acc = 0;
        for (int j = (int)threadIdx.x; j < b; j += 32) acc += g_bsums[j];
        #pragma unroll
        for (int off = 16; off > 0; off >>= 1)
            acc += __shfl_xor_sync(0xffffffffu, acc, off);
        if (threadIdx.x == 0) s_base = acc;
    }
    __syncthreads();
    int i = b * 1024 + threadIdx.x;
    if (i < NN) {
        int r = g_rowptr[i] + s_base;
        g_rowptr[i] = r;
        g_cursor[i] = r;                           // scatter bumps this directly
    }
    if (i == 0) g_rowptr[NN] = NE;
}

__global__ void scatter_k(const void* __restrict__ ei) {
    int t = blockIdx.x * blockDim.x + threadIdx.x;   // edges 2t, 2t+1
    if (2 * t >= NE) return;
    int s0, s1, d0, d1;
    if (g_is64) {
        longlong2 sv = __ldg(&((const longlong2*)ei)[t]);
        longlong2 dv = __ldg(&((const longlong2*)((const long long*)ei + NE))[t]);
        s0 = (int)sv.x; s1 = (int)sv.y;
        d0 = (int)dv.x; d1 = (int)dv.y;
    } else {
        int2 sv = __ldg(&((const int2*)ei)[t]);
        int2 dv = __ldg(&((const int2*)((const int*)ei + NE))[t]);
        s0 = sv.x; s1 = sv.y;
        d0 = dv.x; d1 = dv.y;
    }
    int p0 = atomicAdd(&g_cursor[d0], 1);
    g_csr_src[p0] = s0;
    int p1 = atomicAdd(&g_cursor[d1], 1);
    g_csr_src[p1] = s1;
}

// ---------------- dual GEMM: OL = X @ Wl, OR = X @ Wr  (X: [NN,K], W: [K,32]) --
// Packed f32x2 FMAs; weights staged pre-packed as (w[k],w[k+1]) pairs, x rows
// read as ulonglong2 (one LDS.128 = two f32x2 operands).
template <int K>
__global__ void gemm_dual_k(const float* __restrict__ X,
                            const float* __restrict__ Wl,
                            const float* __restrict__ Wr,
                            float* __restrict__ OL,
                            float* __restrict__ ORr) {
    constexpr int TN = 64;                  // nodes per block
    extern __shared__ float smem[];
    float* s_x  = smem;                     // TN*K
    float* s_wl = smem + TN * K;            // K*32 floats (packed pairs)
    float* s_wr = s_wl + K * 32;            // K*32

    int tid = threadIdx.x;                  // 256 threads
    for (int idx = tid; idx < (K / 2) * 32; idx += 256) {
        int k2 = idx >> 5, l = idx & 31;
        float2 vl = make_float2(Wl[(2 * k2) * 32 + l], Wl[(2 * k2 + 1) * 32 + l]);
        float2 vr = make_float2(Wr[(2 * k2) * 32 + l], Wr[(2 * k2 + 1) * 32 + l]);
        reinterpret_cast<float2*>(s_wl)[idx] = vl;
        reinterpret_cast<float2*>(s_wr)[idx] = vr;
    }
    int nb = blockIdx.x * TN;
    const float4* X4 = reinterpret_cast<const float4*>(X);
    float4* sx4 = reinterpret_cast<float4*>(s_x);
    int base4 = nb * (K / 4);
    int lim4 = NN * (K / 4) - base4;        // valid float4s left in X
    for (int idx = tid; idx < TN * (K / 4); idx += 256) {
        sx4[idx] = (idx < lim4) ? X4[base4 + idx] : make_float4(0.f, 0.f, 0.f, 0.f);
    }
    __syncthreads();

    int w = tid >> 5, lane = tid & 31;
    u64 aL[8], aR[8];
    #pragma unroll
    for (int j = 0; j < 8; j++) { aL[j] = 0ull; aR[j] = 0ull; }
    const float* xrow = &s_x[(w * 8) * K];
    const u64* wl2 = reinterpret_cast<const u64*>(s_wl);
    const u64* wr2 = reinterpret_cast<const u64*>(s_wr);

    #pragma unroll 4
    for (int i = 0; i < K; i += 4) {
        u64 wl01 = wl2[(i >> 1) * 32 + lane];
        u64 wl23 = wl2[((i >> 1) + 1) * 32 + lane];
        u64 wr01 = wr2[(i >> 1) * 32 + lane];
        u64 wr23 = wr2[((i >> 1) + 1) * 32 + lane];
        #pragma unroll
        for (int j = 0; j < 8; j++) {
            ulonglong2 xv = *reinterpret_cast<const ulonglong2*>(&xrow[j * K + i]);
            aL[j] = fma2(xv.x, wl01, aL[j]);
            aL[j] = fma2(xv.y, wl23, aL[j]);
            aR[j] = fma2(xv.x, wr01, aR[j]);
            aR[j] = fma2(xv.y, wr23, aR[j]);
        }
    }
    #pragma unroll
    for (int j = 0; j < 8; j++) {
        int node = nb + w * 8 + j;
        if (node < NN) {
            OL[node * 32 + lane]  = unpack_sum(aL[j]);
            ORr[node * 32 + lane] = unpack_sum(aR[j]);
        }
    }
}

// ---------------- GATv2 edge pass ----------------
// 4 nodes per warp: each 8-lane group owns ONE node and its full contiguous
// edge list (float4 features per lane). No cross-group merge: post-butterfly
// logits (and therefore ssum) are uniform within the group, so each group
// normalizes and stores its node directly. Index loads for the next 4-edge
// iteration are prefetched before processing the current one (software
// pipeline), halving the idx->gather serial latency chain. Softmax without
// max subtraction (logits bounded; acc/s cancels scale exactly).
template <bool RELU>
__global__ void gat_edge_k(const float* __restrict__ xl,
                           const float* __restrict__ xr,
                           const float* __restrict__ att,
                           const float* __restrict__ bias,
                           float* __restrict__ out) {
    int gwarp = (blockIdx.x * blockDim.x + threadIdx.x) >> 5;
    int lane = threadIdx.x & 31;
    int grp = lane >> 3;                    // 0..3 -> node within warp
    int sub = lane & 7;                     // 0..7 -> features sub*4..sub*4+3
    int n = gwarp * 4 + grp;
    if (n >= NN) return;                    // uniform within the group
    const unsigned gmask = 0xffu << (grp * 8);   // this group's 8 lanes

    float4 xr4 = *reinterpret_cast<const float4*>(&xr[n * 32 + sub * 4]);
    float4 at4 = *reinterpret_cast<const float4*>(&att[sub * 4]);

    int e0 = g_rowptr[n], e1 = g_rowptr[n + 1];

    float ssum = 0.f;
    float4 acc = make_float4(0.f, 0.f, 0.f, 0.f);

    int e = e0;
    int s0 = 0, s1 = 0, s2 = 0, s3 = 0;
    if (e + 4 <= e1) {                      // prime the index pipeline
        s0 = __ldg(&g_csr_src[e]);
        s1 = __ldg(&g_csr_src[e + 1]);
        s2 = __ldg(&g_csr_src[e + 2]);
        s3 = __ldg(&g_csr_src[e + 3]);
    }
    while (e + 4 <= e1) {
        int c0 = s0, c1 = s1, c2 = s2, c3 = s3;
        int en = e + 4;
        if (en + 4 <= e1) {                 // prefetch next iteration's indices
            s0 = __ldg(&g_csr_src[en]);
            s1 = __ldg(&g_csr_src[en + 1]);
            s2 = __ldg(&g_csr_src[en + 2]);
            s3 = __ldg(&g_csr_src[en + 3]);
        }
        float4 x0 = *reinterpret_cast<const float4*>(&xl[c0 * 32 + sub * 4]);
        float4 x1 = *reinterpret_cast<const float4*>(&xl[c1 * 32 + sub * 4]);
        float4 x2 = *reinterpret_cast<const float4*>(&xl[c2 * 32 + sub * 4]);
        float4 x3 = *reinterpret_cast<const float4*>(&xl[c3 * 32 + sub * 4]);
        float d0, d1, d2, d3;
        d0  = lrelu(x0.x + xr4.x) * at4.x;
        d0 += lrelu(x0.y + xr4.y) * at4.y;
        d0 += lrelu(x0.z + xr4.z) * at4.z;
        d0 += lrelu(x0.w + xr4.w) * at4.w;
        d1  = lrelu(x1.x + xr4.x) * at4.x;
        d1 += lrelu(x1.y + xr4.y) * at4.y;
        d1 += lrelu(x1.z + xr4.z) * at4.z;
        d1 += lrelu(x1.w + xr4.w) * at4.w;
        d2  = lrelu(x2.x + xr4.x) * at4.x;
        d2 += lrelu(x2.y + xr4.y) * at4.y;
        d2 += lrelu(x2.z + xr4.z) * at4.z;
        d2 += lrelu(x2.w + xr4.w) * at4.w;
        d3  = lrelu(x3.x + xr4.x) * at4.x;
        d3 += lrelu(x3.y + xr4.y) * at4.y;
        d3 += lrelu(x3.z + xr4.z) * at4.z;
        d3 += lrelu(x3.w + xr4.w) * at4.w;
        d0 += __shfl_xor_sync(gmask, d0, 1);
        d1 += __shfl_xor_sync(gmask, d1, 1);
        d2 += __shfl_xor_sync(gmask, d2, 1);
        d3 += __shfl_xor_sync(gmask, d3, 1);
        d0 += __shfl_xor_sync(gmask, d0, 2);
        d1 += __shfl_xor_sync(gmask, d1, 2);
        d2 += __shfl_xor_sync(gmask, d2, 2);
        d3 += __shfl_xor_sync(gmask, d3, 2);
        d0 += __shfl_xor_sync(gmask, d0, 4);
        d1 += __shfl_xor_sync(gmask, d1, 4);
        d2 += __shfl_xor_sync(gmask, d2, 4);
        d3 += __shfl_xor_sync(gmask, d3, 4);
        float ex0 = __expf(d0), ex1 = __expf(d1);
        float ex2 = __expf(d2), ex3 = __expf(d3);
        ssum += (ex0 + ex1) + (ex2 + ex3);
        acc.x = fmaf(ex0, x0.x, fmaf(ex1, x1.x, fmaf(ex2, x2.x, fmaf(ex3, x3.x, acc.x))));
        acc.y = fmaf(ex0, x0.y, fmaf(ex1, x1.y, fmaf(ex2, x2.y, fmaf(ex3, x3.y, acc.y))));
        acc.z = fmaf(ex0, x0.z, fmaf(ex1, x1.z, fmaf(ex2, x2.z, fmaf(ex3, x3.z, acc.z))));
        acc.w = fmaf(ex0, x0.w, fmaf(ex1, x1.w, fmaf(ex2, x2.w, fmaf(ex3, x3.w, acc.w))));
        e = en;
    }
    for (; e < e1; e++) {                   // tail: up to 3 single edges
        int c0 = __ldg(&g_csr_src[e]);
        float4 x0 = *reinterpret_cast<const float4*>(&xl[c0 * 32 + sub * 4]);
        float d0;
        d0  = lrelu(x0.x + xr4.x) * at4.x;
        d0 += lrelu(x0.y + xr4.y) * at4.y;
        d0 += lrelu(x0.z + xr4.z) * at4.z;
        d0 += lrelu(x0.w + xr4.w) * at4.w;
        d0 += __shfl_xor_sync(gmask, d0, 1);
        d0 += __shfl_xor_sync(gmask, d0, 2);
        d0 += __shfl_xor_sync(gmask, d0, 4);
        float ex0 = __expf(d0);
        ssum += ex0;
        acc.x = fmaf(ex0, x0.x, acc.x);
        acc.y = fmaf(ex0, x0.y, acc.y);
        acc.z = fmaf(ex0, x0.z, acc.z);
        acc.w = fmaf(ex0, x0.w, acc.w);
    }

    // ssum is uniform within the group; store directly (no cross-group merge)
    float4 b4 = *reinterpret_cast<const float4*>(&bias[sub * 4]);
    float inv = 1.f / (ssum + 1e-16f);
    float4 o;
    o.x = acc.x * inv + b4.x;
    o.y = acc.y * inv + b4.y;
    o.z = acc.z * inv + b4.z;
    o.w = acc.w * inv + b4.w;
    if (RELU) {
        o.x = fmaxf(o.x, 0.f); o.y = fmaxf(o.y, 0.f);
        o.z = fmaxf(o.z, 0.f); o.w = fmaxf(o.w, 0.f);
    }
    *reinterpret_cast<float4*>(&out[n * 32 + sub * 4]) = o;
}

// ---------------- launch ----------------
extern "C" void kernel_launch(void* const* d_in, const int* in_sizes, int n_in,
                              void* d_out, int out_size) {
    const float* x    = (const float*)d_in[0];
    const void*  ei   = d_in[1];
    const float* W1l  = (const float*)d_in[2];
    const float* W1r  = (const float*)d_in[3];
    const float* att1 = (const float*)d_in[4];
    const float* b1   = (const float*)d_in[5];
    const float* W2l  = (const float*)d_in[6];
    const float* W2r  = (const float*)d_in[7];
    const float* att2 = (const float*)d_in[8];
    const float* b2   = (const float*)d_in[9];
    float* out = (float*)d_out;

    float *p_xl, *p_xr, *p_h;
    int *p_deg;
    cudaGetSymbolAddress((void**)&p_xl, g_xl);
    cudaGetSymbolAddress((void**)&p_xr, g_xr);
    cudaGetSymbolAddress((void**)&p_h,  g_h);
    cudaGetSymbolAddress((void**)&p_deg, g_deg);

    cudaFuncSetAttribute(gemm_dual_k<128>,
                         cudaFuncAttributeMaxDynamicSharedMemorySize, 65536);
    cudaFuncSetAttribute(gemm_dual_k<32>,
                         cudaFuncAttributeMaxDynamicSharedMemorySize, 16384);

    // One-time handle creation (no device memory; work per call is identical).
    // First call is the uncaptured correctness run, so creation is outside
    // graph capture.
    static cudaStream_t sCsr = nullptr;
    static cudaEvent_t evFork = nullptr, evCsr = nullptr;
    if (sCsr == nullptr) {
        cudaStreamCreateWithFlags(&sCsr, cudaStreamNonBlocking);
        cudaEventCreateWithFlags(&evFork, cudaEventDisableTiming);
        cudaEventCreateWithFlags(&evCsr, cudaEventDisableTiming);
    }

    const int nscan = (NN + 1023) / 1024;   // 98
    const int nEdgeWarp = (NN + 3) / 4;     // 4 nodes per warp
    const int nEdgeBlk = (nEdgeWarp * 32 + 255) / 256;

    // Fork: CSR build on side stream, GEMM1 on main stream (independent).
    cudaEventRecord(evFork, 0);
    cudaStreamWaitEvent(sCsr, evFork, 0);

    cudaMemsetAsync(p_deg, 0, NN * sizeof(int), sCsr);
    detect_k<<<1, 256, 0, sCsr>>>((const unsigned int*)ei);
    hist_k<<<(NE / 2 + 255) / 256, 256, 0, sCsr>>>(ei);
    scan_local_k<<<nscan, 1024, 0, sCsr>>>();
    add_offsets_k<<<nscan, 1024, 0, sCsr>>>();
    scatter_k<<<(NE / 2 + 255) / 256, 256, 0, sCsr>>>(ei);
    cudaEventRecord(evCsr, sCsr);

    gemm_dual_k<128><<<(NN + 63) / 64, 256, 65536>>>(x, W1l, W1r, p_xl, p_xr);

    // Join: edge pass needs both CSR and GEMM1.
    cudaStreamWaitEvent(0, evCsr, 0);
    gat_edge_k<true><<<nEdgeBlk, 256>>>(p_xl, p_xr, att1, b1, p_h);

    // Layer 2
    gemm_dual_k<32><<<(NN + 63) / 64, 256, 16384>>>(p_h, W2l, W2r, p_xl, p_xr);
    gat_edge_k<false><<<nEdgeBlk, 256>>>(p_xl, p_xr, att2, b2, out);
}

// round 17
// speedup vs baseline: 1.1231x; 1.1225x over previous
#include <cuda_runtime.h>
#include <math.h>

// Problem constants (fixed shapes per reference)
#define NN 100000          // nodes
#define NE 1600000         // edges
#define DIN 128
#define DHID 32
#define NEG_SLOPE 0.2f

typedef unsigned long long u64;

#define NSCAN ((NN + 1023) / 1024)          // 98 scan blocks

// ---------------- device scratch (static allocation, allowed) ----------------
__device__ int   g_deg[NN];                 // zero at start of every call:
                                            // BSS-zero on first, self-cleaned by scan_fused_k
__device__ int   g_cursor[NN];
__device__ int   g_rowptr[NN + 1];
__device__ volatile int g_st[128];          // lookback state: 0 invalid / AGG|v / INC|v
__device__ int   g_csr_src[NE];
__device__ int   g_is64;                    // 1 if edge_index is int64, 0 if int32
__device__ float g_xl[NN * DHID];
__device__ float g_xr[NN * DHID];
__device__ float g_h[NN * DHID];

#define ST_AGG (1 << 29)
#define ST_INC (2 << 29)
#define ST_VAL ((1 << 29) - 1)              // NE < 2^29 so values fit

// ---------------- f32x2 packed math (Blackwell FFMA2, PTX-only) --------------
__device__ __forceinline__ u64 fma2(u64 a, u64 b, u64 c) {
    u64 d;
    asm("fma.rn.f32x2 %0, %1, %2, %3;" : "=l"(d) : "l"(a), "l"(b), "l"(c));
    return d;
}
__device__ __forceinline__ float unpack_sum(u64 a) {
    float lo, hi;
    asm("mov.b64 {%0,%1}, %2;" : "=f"(lo), "=f"(hi) : "l"(a));
    return lo + hi;
}

// att_k * leaky_relu(h) accumulated via lrelu(h) = 0.6h + 0.4|h|
// (exact identity; |h| is a free FFMA operand modifier)
__device__ __forceinline__ float dot4(float4 x, float4 xr, float4 a6, float4 a4) {
    float h0 = x.x + xr.x, h1 = x.y + xr.y, h2 = x.z + xr.z, h3 = x.w + xr.w;
    float d = fmaf(a6.x, h0, a4.x * fabsf(h0));
    d = fmaf(a6.y, h1, fmaf(a4.y, fabsf(h1), d));
    d = fmaf(a6.z, h2, fmaf(a4.z, fabsf(h2), d));
    d = fmaf(a6.w, h3, fmaf(a4.w, fabsf(h3), d));
    return d;
}

// ---------------- edge dtype detection ----------------
// int64 values < 2^31 => every odd 32-bit word is 0. int32 data: essentially
// impossible for 2048 sampled odd words to all be zero.
__global__ void detect_k(const unsigned int* __restrict__ w) {
    __shared__ int allz;
    if (threadIdx.x == 0) allz = 1;
    __syncthreads();
    for (int k = threadIdx.x; k < 2048; k += blockDim.x) {
        if (w[2 * k + 1] != 0u) allz = 0;
    }
    __syncthreads();
    if (threadIdx.x == 0) g_is64 = allz;
}

// ---------------- CSR build ----------------
// 4 edges per thread. Block 0 also resets the lookback state words for the
// scan kernel that follows (kernel boundary orders it).
__global__ void hist_k(const void* __restrict__ ei) {
    if (blockIdx.x == 0 && threadIdx.x < 128) g_st[threadIdx.x] = 0;
    int t = blockIdx.x * blockDim.x + threadIdx.x;   // edges 4t..4t+3
    if (4 * t >= NE) return;
    int d0, d1, d2, d3;
    if (g_is64) {
        const longlong2* p = (const longlong2*)((const long long*)ei + NE);
        longlong2 va = __ldg(&p[2 * t]);
        longlong2 vb = __ldg(&p[2 * t + 1]);
        d0 = (int)va.x; d1 = (int)va.y; d2 = (int)vb.x; d3 = (int)vb.y;
    } else {
        int4 v = __ldg(&((const int4*)((const int*)ei + NE))[t]);
        d0 = v.x; d1 = v.y; d2 = v.z; d3 = v.w;
    }
    atomicAdd(&g_deg[d0], 1);
    atomicAdd(&g_deg[d1], 1);
    atomicAdd(&g_deg[d2], 1);
    atomicAdd(&g_deg[d3], 1);
}

// Single-pass exclusive scan of g_deg into g_rowptr/g_cursor with decoupled
// lookback (98 blocks). Every block posts its AGGregate before any lookback
// wait, so progress is guaranteed in any scheduling order. Also zeroes g_deg
// for the next replay.
__global__ void scan_fused_k() {            // grid: NSCAN, block: 1024
    __shared__ int wsum[32];
    __shared__ int s_base;
    const unsigned FULL = 0xffffffffu;
    int tid = threadIdx.x, b = blockIdx.x;
    int i = b * 1024 + tid;
    int v = (i < NN) ? g_deg[i] : 0;
    if (i < NN) g_deg[i] = 0;               // self-clean for next call
    int lane = tid & 31, wid = tid >> 5;
    int x = v;
    #pragma unroll
    for (int off = 1; off < 32; off <<= 1) {       // inclusive warp scan
        int t = __shfl_up_sync(FULL, x, off);
        if (lane >= off) x += t;
    }
    if (lane == 31) wsum[wid] = x;
    __syncthreads();
    if (wid == 0) {
        int s = wsum[lane];
        #pragma unroll
        for (int off = 1; off < 32; off <<= 1) {
            int t = __shfl_up_sync(FULL, s, off);
            if (lane >= off) s += t;
        }
        wsum[lane] = s;
    }
    __syncthreads();
    int incl = x + (wid > 0 ? wsum[wid - 1] : 0);
    int total = wsum[31];

    if (tid == 0 && b > 0)
        atomicExch((int*)&g_st[b], ST_AGG | total);   // post aggregate early

    if (wid == 0) {                          // lookback by warp 0
        int exc = 0;
        if (b > 0) {
            int j = b - 1;
            while (true) {
                int jj = j - lane;           // lane 0 = nearest predecessor
                int st;
                do {
                    st = (jj >= 0) ? g_st[jj] : (ST_INC | 0);
                } while (st == 0);
                unsigned incmask = __ballot_sync(FULL, (st & ST_INC) != 0);
                int firstinc = __ffs(incmask) - 1;   // -1 if none
                int lim = (firstinc >= 0) ? firstinc : 31;
                int contrib = (lane <= lim) ? (st & ST_VAL) : 0;
                #pragma unroll
                for (int off = 16; off > 0; off >>= 1)
                    contrib += __shfl_xor_sync(FULL, contrib, off);
                exc += contrib;
                if (firstinc >= 0) break;
                j -= 32;                     // lanes with jj<0 return INC|0 -> always terminates
            }
        }
        if (lane == 0) {
            s_base = exc;
            atomicExch((int*)&g_st[b], ST_INC | (exc + total));
        }
    }
    __syncthreads();
    if (i < NN) {
        int r = incl - v + s_base;          // exclusive prefix + cross-block base
        g_rowptr[i] = r;
        g_cursor[i] = r;                    // scatter bumps this directly
    }
    if (i == 0) g_rowptr[NN] = NE;
}

__global__ void scatter_k(const void* __restrict__ ei) {
    int t = blockIdx.x * blockDim.x + threadIdx.x;   // edges 4t..4t+3
    if (4 * t >= NE) return;
    int s0, s1, s2, s3, d0, d1, d2, d3;
    if (g_is64) {
        const longlong2* ps = (const longlong2*)ei;
        const longlong2* pd = (const longlong2*)((const long long*)ei + NE);
        longlong2 sa = __ldg(&ps[2 * t]), sb = __ldg(&ps[2 * t + 1]);
        longlong2 da = __ldg(&pd[2 * t]), db = __ldg(&pd[2 * t + 1]);
        s0 = (int)sa.x; s1 = (int)sa.y; s2 = (int)sb.x; s3 = (int)sb.y;
        d0 = (int)da.x; d1 = (int)da.y; d2 = (int)db.x; d3 = (int)db.y;
    } else {
        int4 sv = __ldg(&((const int4*)ei)[t]);
        int4 dv = __ldg(&((const int4*)((const int*)ei + NE))[t]);
        s0 = sv.x; s1 = sv.y; s2 = sv.z; s3 = sv.w;
        d0 = dv.x; d1 = dv.y; d2 = dv.z; d3 = dv.w;
    }
    g_csr_src[atomicAdd(&g_cursor[d0], 1)] = s0;
    g_csr_src[atomicAdd(&g_cursor[d1], 1)] = s1;
    g_csr_src[atomicAdd(&g_cursor[d2], 1)] = s2;
    g_csr_src[atomicAdd(&g_cursor[d3], 1)] = s3;
}

// ---------------- dual GEMM: OL = X @ Wl, OR = X @ Wr  (X: [NN,K], W: [K,32]) --
// Packed f32x2 FMAs; weights staged pre-packed as (w[k],w[k+1]) pairs, x rows
// read as ulonglong2 (one LDS.128 = two f32x2 operands).
template <int K>
__global__ void gemm_dual_k(const float* __restrict__ X,
                            const float* __restrict__ Wl,
                            const float* __restrict__ Wr,
                            float* __restrict__ OL,
                            float* __restrict__ ORr) {
    constexpr int TN = 64;                  // nodes per block
    extern __shared__ float smem[];
    float* s_x  = smem;                     // TN*K
    float* s_wl = smem + TN * K;            // K*32 floats (packed pairs)
    float* s_wr = s_wl + K * 32;            // K*32

    int tid = threadIdx.x;                  // 256 threads
    for (int idx = tid; idx < (K / 2) * 32; idx += 256) {
        int k2 = idx >> 5, l = idx & 31;
        float2 vl = make_float2(Wl[(2 * k2) * 32 + l], Wl[(2 * k2 + 1) * 32 + l]);
        float2 vr = make_float2(Wr[(2 * k2) * 32 + l], Wr[(2 * k2 + 1) * 32 + l]);
        reinterpret_cast<float2*>(s_wl)[idx] = vl;
        reinterpret_cast<float2*>(s_wr)[idx] = vr;
    }
    int nb = blockIdx.x * TN;
    const float4* X4 = reinterpret_cast<const float4*>(X);
    float4* sx4 = reinterpret_cast<float4*>(s_x);
    int base4 = nb * (K / 4);
    int lim4 = NN * (K / 4) - base4;        // valid float4s left in X
    for (int idx = tid; idx < TN * (K / 4); idx += 256) {
        sx4[idx] = (idx < lim4) ? X4[base4 + idx] : make_float4(0.f, 0.f, 0.f, 0.f);
    }
    __syncthreads();

    int w = tid >> 5, lane = tid & 31;
    u64 aL[8], aR[8];
    #pragma unroll
    for (int j = 0; j < 8; j++) { aL[j] = 0ull; aR[j] = 0ull; }
    const float* xrow = &s_x[(w * 8) * K];
    const u64* wl2 = reinterpret_cast<const u64*>(s_wl);
    const u64* wr2 = reinterpret_cast<const u64*>(s_wr);

    #pragma unroll 4
    for (int i = 0; i < K; i += 4) {
        u64 wl01 = wl2[(i >> 1) * 32 + lane];
        u64 wl23 = wl2[((i >> 1) + 1) * 32 + lane];
        u64 wr01 = wr2[(i >> 1) * 32 + lane];
        u64 wr23 = wr2[((i >> 1) + 1) * 32 + lane];
        #pragma unroll
        for (int j = 0; j < 8; j++) {
            ulonglong2 xv = *reinterpret_cast<const ulonglong2*>(&xrow[j * K + i]);
            aL[j] = fma2(xv.x, wl01, aL[j]);
            aL[j] = fma2(xv.y, wl23, aL[j]);
            aR[j] = fma2(xv.x, wr01, aR[j]);
            aR[j] = fma2(xv.y, wr23, aR[j]);
        }
    }
    #pragma unroll
    for (int j = 0; j < 8; j++) {
        int node = nb + w * 8 + j;
        if (node < NN) {
            OL[node * 32 + lane]  = unpack_sum(aL[j]);
            ORr[node * 32 + lane] = unpack_sum(aR[j]);
        }
    }
}

// ---------------- GATv2 edge pass ----------------
// 4 nodes per warp: each 8-lane group owns ONE node and its full contiguous
// edge list (float4 features per lane). Post-butterfly logits (and ssum) are
// uniform within the group -> direct per-group store, no cross-group merge.
// Next iteration's indices prefetched (software pipeline). Softmax without
// max subtraction (logits bounded; acc/s cancels scale exactly). Dot uses
// lrelu(h)=0.6h+0.4|h| with att folded into the constants.
template <bool RELU>
__global__ void gat_edge_k(const float* __restrict__ xl,
                           const float* __restrict__ xr,
                           const float* __restrict__ att,
                           const float* __restrict__ bias,
                           float* __restrict__ out) {
    int gwarp = (blockIdx.x * blockDim.x + threadIdx.x) >> 5;
    int lane = threadIdx.x & 31;
    int grp = lane >> 3;                    // 0..3 -> node within warp
    int sub = lane & 7;                     // 0..7 -> features sub*4..sub*4+3
    int n = gwarp * 4 + grp;
    if (n >= NN) return;                    // uniform within the group
    const unsigned gmask = 0xffu << (grp * 8);   // this group's 8 lanes

    float4 xr4 = *reinterpret_cast<const float4*>(&xr[n * 32 + sub * 4]);
    float4 at4 = *reinterpret_cast<const float4*>(&att[sub * 4]);
    float4 a6 = make_float4(0.6f * at4.x, 0.6f * at4.y, 0.6f * at4.z, 0.6f * at4.w);
    float4 a4 = make_float4(0.4f * at4.x, 0.4f * at4.y, 0.4f * at4.z, 0.4f * at4.w);

    int e0 = g_rowptr[n], e1 = g_rowptr[n + 1];

    float ssum = 0.f;
    float4 acc = make_float4(0.f, 0.f, 0.f, 0.f);

    int e = e0;
    int s0 = 0, s1 = 0, s2 = 0, s3 = 0;
    if (e + 4 <= e1) {                      // prime the index pipeline
        s0 = __ldg(&g_csr_src[e]);
        s1 = __ldg(&g_csr_src[e + 1]);
        s2 = __ldg(&g_csr_src[e + 2]);
        s3 = __ldg(&g_csr_src[e + 3]);
    }
    while (e + 4 <= e1) {
        int c0 = s0, c1 = s1, c2 = s2, c3 = s3;
        int en = e + 4;
        if (en + 4 <= e1) {                 // prefetch next iteration's indices
            s0 = __ldg(&g_csr_src[en]);
            s1 = __ldg(&g_csr_src[en + 1]);
            s2 = __ldg(&g_csr_src[en + 2]);
            s3 = __ldg(&g_csr_src[en + 3]);
        }
        float4 x0 = *reinterpret_cast<const float4*>(&xl[c0 * 32 + sub * 4]);
        float4 x1 = *reinterpret_cast<const float4*>(&xl[c1 * 32 + sub * 4]);
        float4 x2 = *reinterpret_cast<const float4*>(&xl[c2 * 32 + sub * 4]);
        float4 x3 = *reinterpret_cast<const float4*>(&xl[c3 * 32 + sub * 4]);
        float d0 = dot4(x0, xr4, a6, a4);
        float d1 = dot4(x1, xr4, a6, a4);
        float d2 = dot4(x2, xr4, a6, a4);
        float d3 = dot4(x3, xr4, a6, a4);
        d0 += __shfl_xor_sync(gmask, d0, 1);
        d1 += __shfl_xor_sync(gmask, d1, 1);
        d2 += __shfl_xor_sync(gmask, d2, 1);
        d3 += __shfl_xor_sync(gmask, d3, 1);
        d0 += __shfl_xor_sync(gmask, d0, 2);
        d1 += __shfl_xor_sync(gmask, d1, 2);
        d2 += __shfl_xor_sync(gmask, d2, 2);
        d3 += __shfl_xor_sync(gmask, d3, 2);
        d0 += __shfl_xor_sync(gmask, d0, 4);
        d1 += __shfl_xor_sync(gmask, d1, 4);
        d2 += __shfl_xor_sync(gmask, d2, 4);
        d3 += __shfl_xor_sync(gmask, d3, 4);
        float ex0 = __expf(d0), ex1 = __expf(d1);
        float ex2 = __expf(d2), ex3 = __expf(d3);
        ssum += (ex0 + ex1) + (ex2 + ex3);
        acc.x = fmaf(ex0, x0.x, fmaf(ex1, x1.x, fmaf(ex2, x2.x, fmaf(ex3, x3.x, acc.x))));
        acc.y = fmaf(ex0, x0.y, fmaf(ex1, x1.y, fmaf(ex2, x2.y, fmaf(ex3, x3.y, acc.y))));
        acc.z = fmaf(ex0, x0.z, fmaf(ex1, x1.z, fmaf(ex2, x2.z, fmaf(ex3, x3.z, acc.z))));
        acc.w = fmaf(ex0, x0.w, fmaf(ex1, x1.w, fmaf(ex2, x2.w, fmaf(ex3, x3.w, acc.w))));
        e = en;
    }
    for (; e < e1; e++) {                   // tail: up to 3 single edges
        int c0 = __ldg(&g_csr_src[e]);
        float4 x0 = *reinterpret_cast<const float4*>(&xl[c0 * 32 + sub * 4]);
        float d0 = dot4(x0, xr4, a6, a4);
        d0 += __shfl_xor_sync(gmask, d0, 1);
        d0 += __shfl_xor_sync(gmask, d0, 2);
        d0 += __shfl_xor_sync(gmask, d0, 4);
        float ex0 = __expf(d0);
        ssum += ex0;
        acc.x = fmaf(ex0, x0.x, acc.x);
        acc.y = fmaf(ex0, x0.y, acc.y);
        acc.z = fmaf(ex0, x0.z, acc.z);
        acc.w = fmaf(ex0, x0.w, acc.w);
    }

    // ssum is uniform within the group; store directly (no cross-group merge)
    float4 b4 = *reinterpret_cast<const float4*>(&bias[sub * 4]);
    float inv = 1.f / (ssum + 1e-16f);
    float4 o;
    o.x = acc.x * inv + b4.x;
    o.y = acc.y * inv + b4.y;
    o.z = acc.z * inv + b4.z;
    o.w = acc.w * inv + b4.w;
    if (RELU) {
        o.x = fmaxf(o.x, 0.f); o.y = fmaxf(o.y, 0.f);
        o.z = fmaxf(o.z, 0.f); o.w = fmaxf(o.w, 0.f);
    }
    *reinterpret_cast<float4*>(&out[n * 32 + sub * 4]) = o;
}

// ---------------- launch ----------------
extern "C" void kernel_launch(void* const* d_in, const int* in_sizes, int n_in,
                              void* d_out, int out_size) {
    const float* x    = (const float*)d_in[0];
    const void*  ei   = d_in[1];
    const float* W1l  = (const float*)d_in[2];
    const float* W1r  = (const float*)d_in[3];
    const float* att1 = (const float*)d_in[4];
    const float* b1   = (const float*)d_in[5];
    const float* W2l  = (const float*)d_in[6];
    const float* W2r  = (const float*)d_in[7];
    const float* att2 = (const float*)d_in[8];
    const float* b2   = (const float*)d_in[9];
    float* out = (float*)d_out;

    float *p_xl, *p_xr, *p_h;
    cudaGetSymbolAddress((void**)&p_xl, g_xl);
    cudaGetSymbolAddress((void**)&p_xr, g_xr);
    cudaGetSymbolAddress((void**)&p_h,  g_h);

    cudaFuncSetAttribute(gemm_dual_k<128>,
                         cudaFuncAttributeMaxDynamicSharedMemorySize, 65536);
    cudaFuncSetAttribute(gemm_dual_k<32>,
                         cudaFuncAttributeMaxDynamicSharedMemorySize, 16384);

    // One-time handle creation (no device memory; work per call is identical).
    // First call is the uncaptured correctness run, so creation is outside
    // graph capture.
    static cudaStream_t sCsr = nullptr;
    static cudaEvent_t evFork = nullptr, evCsr = nullptr;
    if (sCsr == nullptr) {
        cudaStreamCreateWithFlags(&sCsr, cudaStreamNonBlocking);
        cudaEventCreateWithFlags(&evFork, cudaEventDisableTiming);
        cudaEventCreateWithFlags(&evCsr, cudaEventDisableTiming);
    }

    const int nEdgeWarp = (NN + 3) / 4;     // 4 nodes per warp
    const int nEdgeBlk = (nEdgeWarp * 32 + 255) / 256;
    const int nE4Blk = (NE / 4 + 255) / 256;

    // Fork: CSR build on side stream, GEMM1 on main stream (independent).
    cudaEventRecord(evFork, 0);
    cudaStreamWaitEvent(sCsr, evFork, 0);

    detect_k<<<1, 256, 0, sCsr>>>((const unsigned int*)ei);
    hist_k<<<nE4Blk, 256, 0, sCsr>>>(ei);
    scan_fused_k<<<NSCAN, 1024, 0, sCsr>>>();
    scatter_k<<<nE4Blk, 256, 0, sCsr>>>(ei);
    cudaEventRecord(evCsr, sCsr);

    gemm_dual_k<128><<<(NN + 63) / 64, 256, 65536>>>(x, W1l, W1r, p_xl, p_xr);

    // Join: edge pass needs both CSR and GEMM1.
    cudaStreamWaitEvent(0, evCsr, 0);
    gat_edge_k<true><<<nEdgeBlk, 256>>>(p_xl, p_xr, att1, b1, p_h);

    // Layer 2
    gemm_dual_k<32><<<(NN + 63) / 64, 256, 16384>>>(p_h, W2l, W2r, p_xl, p_xr);
    gat_edge_k<false><<<nEdgeBlk, 256>>>(p_xl, p_xr, att2, b2, out);
}